// round 5
// baseline (speedup 1.0000x reference)
#include <cuda_runtime.h>

// ---------------------------------------------------------------------------
// BigramTransformer forward, fp32 baseline.
// B=2048 T=64 D=128 H=4 HD=32 L=6 V=256 DFF=512
// ---------------------------------------------------------------------------

#define Bc   2048
#define Tc   64
#define Dc   128
#define Hc   4
#define HDc  32
#define Lc   6
#define Vc   256
#define DFFc 512
#define NTOK (Bc * Tc)          /* 131072 */
#define QKVC (3 * Dc)           /* 384    */

// ------------------------- scratch (device globals) ------------------------
__device__ float g_x   [(size_t)NTOK * Dc];
__device__ float g_h   [(size_t)NTOK * Dc];
__device__ float g_qkv [(size_t)NTOK * QKVC];
__device__ float g_att [(size_t)NTOK * Dc];
__device__ float g_mid [(size_t)NTOK * DFFc];
__device__ float g_wqkv[(size_t)Lc * Dc * QKVC];

// ------------------------- weight repack: [L,H,D,HD]x3 -> [L,D,3*D] --------
__global__ void repack_kernel(const float* __restrict__ Wq,
                              const float* __restrict__ Wk,
                              const float* __restrict__ Wv,
                              float* __restrict__ out)
{
    int i = blockIdx.x * blockDim.x + threadIdx.x;
    const int total = Lc * Hc * Dc * HDc;
    if (i >= total) return;
    int e = i % HDc;
    int d = (i / HDc) % Dc;
    int h = (i / (HDc * Dc)) % Hc;
    int l = i / (HDc * Dc * Hc);
    int src = ((l * Hc + h) * Dc + d) * HDc + e;
    size_t dst = ((size_t)l * Dc + d) * QKVC;
    int col = h * HDc + e;
    out[dst + col]            = Wq[src];
    out[dst + Dc + col]       = Wk[src];
    out[dst + 2 * Dc + col]   = Wv[src];
}

// ------------------------- embedding ---------------------------------------
__global__ void embed_kernel(const int* __restrict__ idx,
                             const float* __restrict__ tok,
                             const float* __restrict__ pos,
                             float* __restrict__ x)
{
    int n = blockIdx.x;        // token index 0..NTOK-1
    int d = threadIdx.x;       // 0..127
    int t = n & (Tc - 1);
    int v = idx[n];
    x[(size_t)n * Dc + d] = tok[v * Dc + d] + pos[t * Dc + d];
}

// ------------------------- layernorm (one block / token) --------------------
__global__ __launch_bounds__(Dc) void ln_kernel(const float* __restrict__ in,
                                                float* __restrict__ out,
                                                const float* __restrict__ gam,
                                                const float* __restrict__ bet)
{
    int n = blockIdx.x;
    int d = threadIdx.x;
    float x = in[(size_t)n * Dc + d];

    float s = x;
    #pragma unroll
    for (int o = 16; o > 0; o >>= 1) s += __shfl_xor_sync(0xffffffffu, s, o);
    __shared__ float ws[4];
    if ((d & 31) == 0) ws[d >> 5] = s;
    __syncthreads();
    float mean = (ws[0] + ws[1] + ws[2] + ws[3]) * (1.0f / Dc);

    float c = x - mean;
    float v = c * c;
    #pragma unroll
    for (int o = 16; o > 0; o >>= 1) v += __shfl_xor_sync(0xffffffffu, v, o);
    __shared__ float ws2[4];
    if ((d & 31) == 0) ws2[d >> 5] = v;
    __syncthreads();
    float var = (ws2[0] + ws2[1] + ws2[2] + ws2[3]) * (1.0f / Dc);

    out[(size_t)n * Dc + d] = c * rsqrtf(var + 1e-5f) * gam[d] + bet[d];
}

// ------------------------- generic SGEMM: C = act(A@W + bias) (+ res) -------
// A: [M,K] row-major, W: [K,N] row-major. M%64==0, N%64==0, K%16==0.
__global__ __launch_bounds__(256) void gemm_kernel(
    const float* __restrict__ A, const float* __restrict__ W,
    const float* __restrict__ bias, const float* __restrict__ res,
    float* __restrict__ C, int M, int N, int K, int relu)
{
    __shared__ float As[64][16];
    __shared__ float Ws[16][64];
    const int tid  = threadIdx.x;
    const int m0   = blockIdx.y * 64;
    const int n0   = blockIdx.x * 64;
    const int ty   = tid >> 4;           // 0..15
    const int tx   = tid & 15;           // 0..15
    const int arow = tid >> 2;           // 0..63
    const int acol = (tid & 3) << 2;     // 0,4,8,12
    const int wrow = tid >> 4;           // 0..15
    const int wcol = (tid & 15) << 2;    // 0..60

    float acc[4][4] = {};

    for (int k0 = 0; k0 < K; k0 += 16) {
        *(float4*)&As[arow][acol] =
            *(const float4*)(A + (size_t)(m0 + arow) * K + k0 + acol);
        *(float4*)&Ws[wrow][wcol] =
            *(const float4*)(W + (size_t)(k0 + wrow) * N + n0 + wcol);
        __syncthreads();
        #pragma unroll
        for (int k = 0; k < 16; k++) {
            float a[4];
            #pragma unroll
            for (int i = 0; i < 4; i++) a[i] = As[ty * 4 + i][k];
            float4 bv = *(const float4*)&Ws[k][tx * 4];
            #pragma unroll
            for (int i = 0; i < 4; i++) {
                acc[i][0] = fmaf(a[i], bv.x, acc[i][0]);
                acc[i][1] = fmaf(a[i], bv.y, acc[i][1]);
                acc[i][2] = fmaf(a[i], bv.z, acc[i][2]);
                acc[i][3] = fmaf(a[i], bv.w, acc[i][3]);
            }
        }
        __syncthreads();
    }

    const int n = n0 + tx * 4;
    float4 bb = make_float4(0.f, 0.f, 0.f, 0.f);
    if (bias) bb = *(const float4*)(bias + n);
    #pragma unroll
    for (int i = 0; i < 4; i++) {
        const size_t m = (size_t)(m0 + ty * 4 + i);
        float4 v = make_float4(acc[i][0] + bb.x, acc[i][1] + bb.y,
                               acc[i][2] + bb.z, acc[i][3] + bb.w);
        if (relu) {
            v.x = fmaxf(v.x, 0.f); v.y = fmaxf(v.y, 0.f);
            v.z = fmaxf(v.z, 0.f); v.w = fmaxf(v.w, 0.f);
        }
        if (res) {
            const float4 r = *(const float4*)(res + m * N + n);
            v.x += r.x; v.y += r.y; v.z += r.z; v.w += r.w;
        }
        *(float4*)(C + m * N + n) = v;
    }
}

// ------------------------- attention: one block per (b,h) -------------------
__global__ __launch_bounds__(Tc) void attn_kernel(const float* __restrict__ qkv,
                                                  float* __restrict__ att)
{
    __shared__ float4 qsm[Tc][HDc / 4];
    __shared__ float4 ksm[Tc][HDc / 4];
    __shared__ float4 vsm[Tc][HDc / 4];

    const int bh  = blockIdx.x;
    const int b   = bh >> 2;          // H = 4
    const int h   = bh & 3;
    const int tid = threadIdx.x;      // = row t, 0..63

    const float* row = qkv + ((size_t)(b * Tc + tid)) * QKVC + h * HDc;
    #pragma unroll
    for (int j = 0; j < 8; j++) {
        qsm[tid][j] = *(const float4*)(row + 4 * j);
        ksm[tid][j] = *(const float4*)(row + Dc + 4 * j);
        vsm[tid][j] = *(const float4*)(row + 2 * Dc + 4 * j);
    }
    __syncthreads();

    const int t = tid;
    float q[HDc];
    #pragma unroll
    for (int j = 0; j < 8; j++) {
        float4 f = qsm[t][j];
        q[4 * j] = f.x; q[4 * j + 1] = f.y; q[4 * j + 2] = f.z; q[4 * j + 3] = f.w;
    }

    const float scale = 0.17677669529663687f;   // 32^-0.5
    float sc[Tc];
    float mx = -1e30f;
    #pragma unroll
    for (int s = 0; s < Tc; s++) {
        float d = 0.f;
        #pragma unroll
        for (int j = 0; j < 8; j++) {
            float4 f = ksm[s][j];
            d = fmaf(q[4 * j],     f.x, d);
            d = fmaf(q[4 * j + 1], f.y, d);
            d = fmaf(q[4 * j + 2], f.z, d);
            d = fmaf(q[4 * j + 3], f.w, d);
        }
        d *= scale;
        sc[s] = d;
        if (s <= t) mx = fmaxf(mx, d);
    }

    float sum = 0.f;
    #pragma unroll
    for (int s = 0; s < Tc; s++) {
        float w = (s <= t) ? __expf(sc[s] - mx) : 0.f;
        sc[s] = w;
        sum += w;
    }
    const float inv = 1.f / sum;

    float4 acc[8] = {};
    #pragma unroll
    for (int s = 0; s < Tc; s++) {
        float w = sc[s];                       // 0 for masked s>t
        #pragma unroll
        for (int j = 0; j < 8; j++) {
            float4 f = vsm[s][j];
            acc[j].x = fmaf(w, f.x, acc[j].x);
            acc[j].y = fmaf(w, f.y, acc[j].y);
            acc[j].z = fmaf(w, f.z, acc[j].z);
            acc[j].w = fmaf(w, f.w, acc[j].w);
        }
    }

    float* outp = att + ((size_t)(b * Tc + t)) * Dc + h * HDc;
    #pragma unroll
    for (int j = 0; j < 8; j++) {
        float4 o = acc[j];
        o.x *= inv; o.y *= inv; o.z *= inv; o.w *= inv;
        *(float4*)(outp + 4 * j) = o;
    }
}

// ------------------------- launcher -----------------------------------------
extern "C" void kernel_launch(void* const* d_in, const int* in_sizes, int n_in,
                              void* d_out, int out_size)
{
    (void)in_sizes; (void)n_in; (void)out_size;
    const int*   idx  = (const int*)  d_in[0];
    const float* tok  = (const float*)d_in[1];
    const float* pos  = (const float*)d_in[2];
    const float* Wq   = (const float*)d_in[3];
    const float* Wk   = (const float*)d_in[4];
    const float* Wv   = (const float*)d_in[5];
    const float* Wo   = (const float*)d_in[6];
    const float* bo   = (const float*)d_in[7];
    const float* ln1g = (const float*)d_in[8];
    const float* ln1b = (const float*)d_in[9];
    const float* W1   = (const float*)d_in[10];
    const float* b1   = (const float*)d_in[11];
    const float* W2   = (const float*)d_in[12];
    const float* b2   = (const float*)d_in[13];
    const float* ln2g = (const float*)d_in[14];
    const float* ln2b = (const float*)d_in[15];
    const float* lnfg = (const float*)d_in[16];
    const float* lnfb = (const float*)d_in[17];
    const float* Wh   = (const float*)d_in[18];
    const float* bh   = (const float*)d_in[19];
    float* out = (float*)d_out;

    float *x, *h, *qkv, *att, *mid, *wqkv;
    cudaGetSymbolAddress((void**)&x,    g_x);
    cudaGetSymbolAddress((void**)&h,    g_h);
    cudaGetSymbolAddress((void**)&qkv,  g_qkv);
    cudaGetSymbolAddress((void**)&att,  g_att);
    cudaGetSymbolAddress((void**)&mid,  g_mid);
    cudaGetSymbolAddress((void**)&wqkv, g_wqkv);

    const int rp_total = Lc * Hc * Dc * HDc;
    repack_kernel<<<(rp_total + 255) / 256, 256>>>(Wq, Wk, Wv, wqkv);
    embed_kernel<<<NTOK, Dc>>>(idx, tok, pos, x);

    const dim3 gQKV (QKVC / 64, NTOK / 64);
    const dim3 gD   (Dc   / 64, NTOK / 64);
    const dim3 gFF  (DFFc / 64, NTOK / 64);
    const dim3 gV   (Vc   / 64, NTOK / 64);

    for (int l = 0; l < Lc; l++) {
        ln_kernel<<<NTOK, Dc>>>(x, h, ln1g + l * Dc, ln1b + l * Dc);
        gemm_kernel<<<gQKV, 256>>>(h, wqkv + (size_t)l * Dc * QKVC,
                                   nullptr, nullptr, qkv, NTOK, QKVC, Dc, 0);
        attn_kernel<<<Bc * Hc, Tc>>>(qkv, att);
        gemm_kernel<<<gD, 256>>>(att, Wo + (size_t)l * Dc * Dc,
                                 bo + l * Dc, x, x, NTOK, Dc, Dc, 0);
        ln_kernel<<<NTOK, Dc>>>(x, h, ln2g + l * Dc, ln2b + l * Dc);
        gemm_kernel<<<gFF, 256>>>(h, W1 + (size_t)l * Dc * DFFc,
                                  b1 + l * DFFc, nullptr, mid, NTOK, DFFc, Dc, 1);
        gemm_kernel<<<gD, 256>>>(mid, W2 + (size_t)l * DFFc * Dc,
                                 b2 + l * Dc, x, x, NTOK, Dc, DFFc, 0);
    }

    ln_kernel<<<NTOK, Dc>>>(x, h, lnfg, lnfb);
    gemm_kernel<<<gV, 256>>>(h, Wh, bh, nullptr, out, NTOK, Vc, Dc, 0);
}

// round 6
// speedup vs baseline: 1.0003x; 1.0003x over previous
#include <cuda_runtime.h>

// ---------------------------------------------------------------------------
// BigramTransformer forward, fp32 baseline.
// B=2048 T=64 D=128 H=4 HD=32 L=6 V=256 DFF=512
// ---------------------------------------------------------------------------

#define Bc   2048
#define Tc   64
#define Dc   128
#define Hc   4
#define HDc  32
#define Lc   6
#define Vc   256
#define DFFc 512
#define NTOK (Bc * Tc)          /* 131072 */
#define QKVC (3 * Dc)           /* 384    */

// ------------------------- scratch (device globals) ------------------------
__device__ float g_x   [(size_t)NTOK * Dc];
__device__ float g_h   [(size_t)NTOK * Dc];
__device__ float g_qkv [(size_t)NTOK * QKVC];
__device__ float g_att [(size_t)NTOK * Dc];
__device__ float g_mid [(size_t)NTOK * DFFc];
__device__ float g_wqkv[(size_t)Lc * Dc * QKVC];

// ------------------------- weight repack: [L,H,D,HD]x3 -> [L,D,3*D] --------
__global__ void repack_kernel(const float* __restrict__ Wq,
                              const float* __restrict__ Wk,
                              const float* __restrict__ Wv,
                              float* __restrict__ out)
{
    int i = blockIdx.x * blockDim.x + threadIdx.x;
    const int total = Lc * Hc * Dc * HDc;
    if (i >= total) return;
    int e = i % HDc;
    int d = (i / HDc) % Dc;
    int h = (i / (HDc * Dc)) % Hc;
    int l = i / (HDc * Dc * Hc);
    int src = ((l * Hc + h) * Dc + d) * HDc + e;
    size_t dst = ((size_t)l * Dc + d) * QKVC;
    int col = h * HDc + e;
    out[dst + col]            = Wq[src];
    out[dst + Dc + col]       = Wk[src];
    out[dst + 2 * Dc + col]   = Wv[src];
}

// ------------------------- embedding ---------------------------------------
__global__ void embed_kernel(const int* __restrict__ idx,
                             const float* __restrict__ tok,
                             const float* __restrict__ pos,
                             float* __restrict__ x)
{
    int n = blockIdx.x;        // token index 0..NTOK-1
    int d = threadIdx.x;       // 0..127
    int t = n & (Tc - 1);
    int v = idx[n];
    x[(size_t)n * Dc + d] = tok[v * Dc + d] + pos[t * Dc + d];
}

// ------------------------- layernorm (one block / token) --------------------
__global__ __launch_bounds__(Dc) void ln_kernel(const float* __restrict__ in,
                                                float* __restrict__ out,
                                                const float* __restrict__ gam,
                                                const float* __restrict__ bet)
{
    int n = blockIdx.x;
    int d = threadIdx.x;
    float x = in[(size_t)n * Dc + d];

    float s = x;
    #pragma unroll
    for (int o = 16; o > 0; o >>= 1) s += __shfl_xor_sync(0xffffffffu, s, o);
    __shared__ float ws[4];
    if ((d & 31) == 0) ws[d >> 5] = s;
    __syncthreads();
    float mean = (ws[0] + ws[1] + ws[2] + ws[3]) * (1.0f / Dc);

    float c = x - mean;
    float v = c * c;
    #pragma unroll
    for (int o = 16; o > 0; o >>= 1) v += __shfl_xor_sync(0xffffffffu, v, o);
    __shared__ float ws2[4];
    if ((d & 31) == 0) ws2[d >> 5] = v;
    __syncthreads();
    float var = (ws2[0] + ws2[1] + ws2[2] + ws2[3]) * (1.0f / Dc);

    out[(size_t)n * Dc + d] = c * rsqrtf(var + 1e-5f) * gam[d] + bet[d];
}

// ------------------------- generic SGEMM: C = act(A@W + bias) (+ res) -------
// A: [M,K] row-major, W: [K,N] row-major. M%64==0, N%64==0, K%16==0.
__global__ __launch_bounds__(256) void gemm_kernel(
    const float* __restrict__ A, const float* __restrict__ W,
    const float* __restrict__ bias, const float* __restrict__ res,
    float* __restrict__ C, int M, int N, int K, int relu)
{
    __shared__ float As[64][16];
    __shared__ float Ws[16][64];
    const int tid  = threadIdx.x;
    const int m0   = blockIdx.y * 64;
    const int n0   = blockIdx.x * 64;
    const int ty   = tid >> 4;           // 0..15
    const int tx   = tid & 15;           // 0..15
    const int arow = tid >> 2;           // 0..63
    const int acol = (tid & 3) << 2;     // 0,4,8,12
    const int wrow = tid >> 4;           // 0..15
    const int wcol = (tid & 15) << 2;    // 0..60

    float acc[4][4] = {};

    for (int k0 = 0; k0 < K; k0 += 16) {
        *(float4*)&As[arow][acol] =
            *(const float4*)(A + (size_t)(m0 + arow) * K + k0 + acol);
        *(float4*)&Ws[wrow][wcol] =
            *(const float4*)(W + (size_t)(k0 + wrow) * N + n0 + wcol);
        __syncthreads();
        #pragma unroll
        for (int k = 0; k < 16; k++) {
            float a[4];
            #pragma unroll
            for (int i = 0; i < 4; i++) a[i] = As[ty * 4 + i][k];
            float4 bv = *(const float4*)&Ws[k][tx * 4];
            #pragma unroll
            for (int i = 0; i < 4; i++) {
                acc[i][0] = fmaf(a[i], bv.x, acc[i][0]);
                acc[i][1] = fmaf(a[i], bv.y, acc[i][1]);
                acc[i][2] = fmaf(a[i], bv.z, acc[i][2]);
                acc[i][3] = fmaf(a[i], bv.w, acc[i][3]);
            }
        }
        __syncthreads();
    }

    const int n = n0 + tx * 4;
    float4 bb = make_float4(0.f, 0.f, 0.f, 0.f);
    if (bias) bb = *(const float4*)(bias + n);
    #pragma unroll
    for (int i = 0; i < 4; i++) {
        const size_t m = (size_t)(m0 + ty * 4 + i);
        float4 v = make_float4(acc[i][0] + bb.x, acc[i][1] + bb.y,
                               acc[i][2] + bb.z, acc[i][3] + bb.w);
        if (relu) {
            v.x = fmaxf(v.x, 0.f); v.y = fmaxf(v.y, 0.f);
            v.z = fmaxf(v.z, 0.f); v.w = fmaxf(v.w, 0.f);
        }
        if (res) {
            const float4 r = *(const float4*)(res + m * N + n);
            v.x += r.x; v.y += r.y; v.z += r.z; v.w += r.w;
        }
        *(float4*)(C + m * N + n) = v;
    }
}

// ------------------------- attention: one block per (b,h) -------------------
__global__ __launch_bounds__(Tc) void attn_kernel(const float* __restrict__ qkv,
                                                  float* __restrict__ att)
{
    __shared__ float4 qsm[Tc][HDc / 4];
    __shared__ float4 ksm[Tc][HDc / 4];
    __shared__ float4 vsm[Tc][HDc / 4];

    const int bh  = blockIdx.x;
    const int b   = bh >> 2;          // H = 4
    const int h   = bh & 3;
    const int tid = threadIdx.x;      // = row t, 0..63

    const float* row = qkv + ((size_t)(b * Tc + tid)) * QKVC + h * HDc;
    #pragma unroll
    for (int j = 0; j < 8; j++) {
        qsm[tid][j] = *(const float4*)(row + 4 * j);
        ksm[tid][j] = *(const float4*)(row + Dc + 4 * j);
        vsm[tid][j] = *(const float4*)(row + 2 * Dc + 4 * j);
    }
    __syncthreads();

    const int t = tid;
    float q[HDc];
    #pragma unroll
    for (int j = 0; j < 8; j++) {
        float4 f = qsm[t][j];
        q[4 * j] = f.x; q[4 * j + 1] = f.y; q[4 * j + 2] = f.z; q[4 * j + 3] = f.w;
    }

    const float scale = 0.17677669529663687f;   // 32^-0.5
    float sc[Tc];
    float mx = -1e30f;
    #pragma unroll
    for (int s = 0; s < Tc; s++) {
        float d = 0.f;
        #pragma unroll
        for (int j = 0; j < 8; j++) {
            float4 f = ksm[s][j];
            d = fmaf(q[4 * j],     f.x, d);
            d = fmaf(q[4 * j + 1], f.y, d);
            d = fmaf(q[4 * j + 2], f.z, d);
            d = fmaf(q[4 * j + 3], f.w, d);
        }
        d *= scale;
        sc[s] = d;
        if (s <= t) mx = fmaxf(mx, d);
    }

    float sum = 0.f;
    #pragma unroll
    for (int s = 0; s < Tc; s++) {
        float w = (s <= t) ? __expf(sc[s] - mx) : 0.f;
        sc[s] = w;
        sum += w;
    }
    const float inv = 1.f / sum;

    float4 acc[8] = {};
    #pragma unroll
    for (int s = 0; s < Tc; s++) {
        float w = sc[s];                       // 0 for masked s>t
        #pragma unroll
        for (int j = 0; j < 8; j++) {
            float4 f = vsm[s][j];
            acc[j].x = fmaf(w, f.x, acc[j].x);
            acc[j].y = fmaf(w, f.y, acc[j].y);
            acc[j].z = fmaf(w, f.z, acc[j].z);
            acc[j].w = fmaf(w, f.w, acc[j].w);
        }
    }

    float* outp = att + ((size_t)(b * Tc + t)) * Dc + h * HDc;
    #pragma unroll
    for (int j = 0; j < 8; j++) {
        float4 o = acc[j];
        o.x *= inv; o.y *= inv; o.z *= inv; o.w *= inv;
        *(float4*)(outp + 4 * j) = o;
    }
}

// ------------------------- launcher -----------------------------------------
extern "C" void kernel_launch(void* const* d_in, const int* in_sizes, int n_in,
                              void* d_out, int out_size)
{
    (void)in_sizes; (void)n_in; (void)out_size;
    const int*   idx  = (const int*)  d_in[0];
    const float* tok  = (const float*)d_in[1];
    const float* pos  = (const float*)d_in[2];
    const float* Wq   = (const float*)d_in[3];
    const float* Wk   = (const float*)d_in[4];
    const float* Wv   = (const float*)d_in[5];
    const float* Wo   = (const float*)d_in[6];
    const float* bo   = (const float*)d_in[7];
    const float* ln1g = (const float*)d_in[8];
    const float* ln1b = (const float*)d_in[9];
    const float* W1   = (const float*)d_in[10];
    const float* b1   = (const float*)d_in[11];
    const float* W2   = (const float*)d_in[12];
    const float* b2   = (const float*)d_in[13];
    const float* ln2g = (const float*)d_in[14];
    const float* ln2b = (const float*)d_in[15];
    const float* lnfg = (const float*)d_in[16];
    const float* lnfb = (const float*)d_in[17];
    const float* Wh   = (const float*)d_in[18];
    const float* bh   = (const float*)d_in[19];
    float* out = (float*)d_out;

    float *x, *h, *qkv, *att, *mid, *wqkv;
    cudaGetSymbolAddress((void**)&x,    g_x);
    cudaGetSymbolAddress((void**)&h,    g_h);
    cudaGetSymbolAddress((void**)&qkv,  g_qkv);
    cudaGetSymbolAddress((void**)&att,  g_att);
    cudaGetSymbolAddress((void**)&mid,  g_mid);
    cudaGetSymbolAddress((void**)&wqkv, g_wqkv);

    const int rp_total = Lc * Hc * Dc * HDc;
    repack_kernel<<<(rp_total + 255) / 256, 256>>>(Wq, Wk, Wv, wqkv);
    embed_kernel<<<NTOK, Dc>>>(idx, tok, pos, x);

    const dim3 gQKV (QKVC / 64, NTOK / 64);
    const dim3 gD   (Dc   / 64, NTOK / 64);
    const dim3 gFF  (DFFc / 64, NTOK / 64);
    const dim3 gV   (Vc   / 64, NTOK / 64);

    for (int l = 0; l < Lc; l++) {
        ln_kernel<<<NTOK, Dc>>>(x, h, ln1g + l * Dc, ln1b + l * Dc);
        gemm_kernel<<<gQKV, 256>>>(h, wqkv + (size_t)l * Dc * QKVC,
                                   nullptr, nullptr, qkv, NTOK, QKVC, Dc, 0);
        attn_kernel<<<Bc * Hc, Tc>>>(qkv, att);
        gemm_kernel<<<gD, 256>>>(att, Wo + (size_t)l * Dc * Dc,
                                 bo + l * Dc, x, x, NTOK, Dc, Dc, 0);
        ln_kernel<<<NTOK, Dc>>>(x, h, ln2g + l * Dc, ln2b + l * Dc);
        gemm_kernel<<<gFF, 256>>>(h, W1 + (size_t)l * Dc * DFFc,
                                  b1 + l * DFFc, nullptr, mid, NTOK, DFFc, Dc, 1);
        gemm_kernel<<<gD, 256>>>(mid, W2 + (size_t)l * DFFc * Dc,
                                 b2 + l * Dc, x, x, NTOK, Dc, DFFc, 0);
    }

    ln_kernel<<<NTOK, Dc>>>(x, h, lnfg, lnfb);
    gemm_kernel<<<gV, 256>>>(h, Wh, bh, nullptr, out, NTOK, Vc, Dc, 0);
}

// round 7
// speedup vs baseline: 1.1903x; 1.1899x over previous
#include <cuda_runtime.h>

// ---------------------------------------------------------------------------
// BigramTransformer forward, fp32, 128x128x16 / 8x8-per-thread SGEMM.
// B=2048 T=64 D=128 H=4 HD=32 L=6 V=256 DFF=512
// ---------------------------------------------------------------------------

#define Bc   2048
#define Tc   64
#define Dc   128
#define Hc   4
#define HDc  32
#define Lc   6
#define Vc   256
#define DFFc 512
#define NTOK (Bc * Tc)          /* 131072 */
#define QKVC (3 * Dc)           /* 384    */

// ------------------------- scratch (device globals) ------------------------
__device__ float g_x   [(size_t)NTOK * Dc];
__device__ float g_h   [(size_t)NTOK * Dc];
__device__ float g_qkv [(size_t)NTOK * QKVC];
__device__ float g_att [(size_t)NTOK * Dc];
__device__ float g_mid [(size_t)NTOK * DFFc];
__device__ float g_wqkv[(size_t)Lc * Dc * QKVC];

// ------------------------- weight repack: [L,H,D,HD]x3 -> [L,D,3*D] --------
__global__ void repack_kernel(const float* __restrict__ Wq,
                              const float* __restrict__ Wk,
                              const float* __restrict__ Wv,
                              float* __restrict__ out)
{
    int i = blockIdx.x * blockDim.x + threadIdx.x;
    const int total = Lc * Hc * Dc * HDc;
    if (i >= total) return;
    int e = i % HDc;
    int d = (i / HDc) % Dc;
    int h = (i / (HDc * Dc)) % Hc;
    int l = i / (HDc * Dc * Hc);
    int src = ((l * Hc + h) * Dc + d) * HDc + e;
    size_t dst = ((size_t)l * Dc + d) * QKVC;
    int col = h * HDc + e;
    out[dst + col]            = Wq[src];
    out[dst + Dc + col]       = Wk[src];
    out[dst + 2 * Dc + col]   = Wv[src];
}

// ------------------------- embedding ---------------------------------------
__global__ void embed_kernel(const int* __restrict__ idx,
                             const float* __restrict__ tok,
                             const float* __restrict__ pos,
                             float* __restrict__ x)
{
    int n = blockIdx.x;        // token index 0..NTOK-1
    int d = threadIdx.x;       // 0..127
    int t = n & (Tc - 1);
    int v = idx[n];
    x[(size_t)n * Dc + d] = tok[v * Dc + d] + pos[t * Dc + d];
}

// ------------------------- layernorm (one warp / token, float4) -------------
__global__ __launch_bounds__(256) void ln_kernel(const float* __restrict__ in,
                                                 float* __restrict__ out,
                                                 const float* __restrict__ gam,
                                                 const float* __restrict__ bet)
{
    const int warp = threadIdx.x >> 5;
    const int lane = threadIdx.x & 31;
    const size_t n = (size_t)blockIdx.x * 8 + warp;   // 8 tokens / block

    float4 v = ((const float4*)(in + n * Dc))[lane];

    float s = v.x + v.y + v.z + v.w;
    #pragma unroll
    for (int o = 16; o > 0; o >>= 1) s += __shfl_xor_sync(0xffffffffu, s, o);
    const float mean = s * (1.0f / Dc);

    float4 c = make_float4(v.x - mean, v.y - mean, v.z - mean, v.w - mean);
    float q = c.x * c.x + c.y * c.y + c.z * c.z + c.w * c.w;
    #pragma unroll
    for (int o = 16; o > 0; o >>= 1) q += __shfl_xor_sync(0xffffffffu, q, o);
    const float r = rsqrtf(q * (1.0f / Dc) + 1e-5f);

    const float4 g = ((const float4*)gam)[lane];
    const float4 b = ((const float4*)bet)[lane];
    float4 o4;
    o4.x = c.x * r * g.x + b.x;
    o4.y = c.y * r * g.y + b.y;
    o4.z = c.z * r * g.z + b.z;
    o4.w = c.w * r * g.w + b.w;
    ((float4*)(out + n * Dc))[lane] = o4;
}

// ------------------------- SGEMM 128x128x16, 8x8/thread ---------------------
// C = act(A@W + bias) (+ res).  A:[M,K] W:[K,N] row-major.
// Requires M%128==0, N%128==0, K%16==0.
__global__ __launch_bounds__(256, 2) void gemm_kernel(
    const float* __restrict__ A, const float* __restrict__ W,
    const float* __restrict__ bias, const float* __restrict__ res,
    float* __restrict__ C, int M, int N, int K, int relu)
{
    __shared__ float As[2][16][132];   // transposed A tile, padded
    __shared__ float Bs[2][16][128];

    const int tid = threadIdx.x;
    const int tx  = tid & 15;          // n-dir, 8 cols each
    const int ty  = tid >> 4;          // m-dir, 8 rows each
    const int m0  = blockIdx.y * 128;
    const int n0  = blockIdx.x * 128;

    // load mapping: 512 float4 per operand tile, 2 per thread
    const int ar0 = tid >> 2;                  // 0..63
    const int ar1 = ar0 + 64;
    const int ac0 = (tid & 3) << 2;            // 0,4,8,12
    const int br0 = tid >> 5;                  // 0..7
    const int br1 = br0 + 8;
    const int bc0 = (tid & 31) << 2;           // 0..124

    const float* Ab = A + (size_t)m0 * K;
    const float* Wb = W + n0;

    float4 pa0, pa1, pb0, pb1;

    // prologue: k0 = 0
    pa0 = *(const float4*)(Ab + (size_t)ar0 * K + ac0);
    pa1 = *(const float4*)(Ab + (size_t)ar1 * K + ac0);
    pb0 = *(const float4*)(Wb + (size_t)br0 * N + bc0);
    pb1 = *(const float4*)(Wb + (size_t)br1 * N + bc0);

    As[0][ac0 + 0][ar0] = pa0.x; As[0][ac0 + 1][ar0] = pa0.y;
    As[0][ac0 + 2][ar0] = pa0.z; As[0][ac0 + 3][ar0] = pa0.w;
    As[0][ac0 + 0][ar1] = pa1.x; As[0][ac0 + 1][ar1] = pa1.y;
    As[0][ac0 + 2][ar1] = pa1.z; As[0][ac0 + 3][ar1] = pa1.w;
    *(float4*)&Bs[0][br0][bc0] = pb0;
    *(float4*)&Bs[0][br1][bc0] = pb1;
    __syncthreads();

    float acc[8][8] = {};
    const int nstep = K >> 4;

    for (int s = 0; s < nstep; s++) {
        const int buf = s & 1;
        const bool more = (s + 1 < nstep);
        if (more) {                       // prefetch next tiles into registers
            const int k0 = (s + 1) << 4;
            pa0 = *(const float4*)(Ab + (size_t)ar0 * K + k0 + ac0);
            pa1 = *(const float4*)(Ab + (size_t)ar1 * K + k0 + ac0);
            pb0 = *(const float4*)(Wb + (size_t)(k0 + br0) * N + bc0);
            pb1 = *(const float4*)(Wb + (size_t)(k0 + br1) * N + bc0);
        }
        #pragma unroll
        for (int k = 0; k < 16; k++) {
            float a[8], b[8];
            *(float4*)(a)     = *(const float4*)&As[buf][k][ty * 8];
            *(float4*)(a + 4) = *(const float4*)&As[buf][k][ty * 8 + 4];
            *(float4*)(b)     = *(const float4*)&Bs[buf][k][tx * 8];
            *(float4*)(b + 4) = *(const float4*)&Bs[buf][k][tx * 8 + 4];
            #pragma unroll
            for (int i = 0; i < 8; i++)
                #pragma unroll
                for (int j = 0; j < 8; j++)
                    acc[i][j] = fmaf(a[i], b[j], acc[i][j]);
        }
        if (more) {                       // store prefetch into the idle buffer
            const int nb = (s + 1) & 1;
            As[nb][ac0 + 0][ar0] = pa0.x; As[nb][ac0 + 1][ar0] = pa0.y;
            As[nb][ac0 + 2][ar0] = pa0.z; As[nb][ac0 + 3][ar0] = pa0.w;
            As[nb][ac0 + 0][ar1] = pa1.x; As[nb][ac0 + 1][ar1] = pa1.y;
            As[nb][ac0 + 2][ar1] = pa1.z; As[nb][ac0 + 3][ar1] = pa1.w;
            *(float4*)&Bs[nb][br0][bc0] = pb0;
            *(float4*)&Bs[nb][br1][bc0] = pb1;
        }
        __syncthreads();
    }

    // epilogue
    const int n = n0 + tx * 8;
    float bv[8] = {};
    if (bias) {
        *(float4*)(bv)     = *(const float4*)(bias + n);
        *(float4*)(bv + 4) = *(const float4*)(bias + n + 4);
    }
    #pragma unroll
    for (int i = 0; i < 8; i++) {
        const size_t m = (size_t)(m0 + ty * 8 + i);
        float v[8];
        #pragma unroll
        for (int j = 0; j < 8; j++) {
            float t = acc[i][j] + bv[j];
            if (relu) t = fmaxf(t, 0.f);
            v[j] = t;
        }
        if (res) {
            const float4 r0 = *(const float4*)(res + m * N + n);
            const float4 r1 = *(const float4*)(res + m * N + n + 4);
            v[0] += r0.x; v[1] += r0.y; v[2] += r0.z; v[3] += r0.w;
            v[4] += r1.x; v[5] += r1.y; v[6] += r1.z; v[7] += r1.w;
        }
        *(float4*)(C + m * N + n)     = *(float4*)(v);
        *(float4*)(C + m * N + n + 4) = *(float4*)(v + 4);
    }
}

// ------------------------- attention: one block per (b,h) -------------------
__global__ __launch_bounds__(Tc) void attn_kernel(const float* __restrict__ qkv,
                                                  float* __restrict__ att)
{
    __shared__ float4 qsm[Tc][HDc / 4];
    __shared__ float4 ksm[Tc][HDc / 4];
    __shared__ float4 vsm[Tc][HDc / 4];

    const int bh  = blockIdx.x;
    const int b   = bh >> 2;          // H = 4
    const int h   = bh & 3;
    const int tid = threadIdx.x;      // = row t, 0..63

    const float* row = qkv + ((size_t)(b * Tc + tid)) * QKVC + h * HDc;
    #pragma unroll
    for (int j = 0; j < 8; j++) {
        qsm[tid][j] = *(const float4*)(row + 4 * j);
        ksm[tid][j] = *(const float4*)(row + Dc + 4 * j);
        vsm[tid][j] = *(const float4*)(row + 2 * Dc + 4 * j);
    }
    __syncthreads();

    const int t = tid;
    float q[HDc];
    #pragma unroll
    for (int j = 0; j < 8; j++) {
        float4 f = qsm[t][j];
        q[4 * j] = f.x; q[4 * j + 1] = f.y; q[4 * j + 2] = f.z; q[4 * j + 3] = f.w;
    }

    const float scale = 0.17677669529663687f;   // 32^-0.5
    float sc[Tc];
    float mx = -1e30f;
    #pragma unroll
    for (int s = 0; s < Tc; s++) {
        float d = 0.f;
        #pragma unroll
        for (int j = 0; j < 8; j++) {
            float4 f = ksm[s][j];
            d = fmaf(q[4 * j],     f.x, d);
            d = fmaf(q[4 * j + 1], f.y, d);
            d = fmaf(q[4 * j + 2], f.z, d);
            d = fmaf(q[4 * j + 3], f.w, d);
        }
        d *= scale;
        sc[s] = d;
        if (s <= t) mx = fmaxf(mx, d);
    }

    float sum = 0.f;
    #pragma unroll
    for (int s = 0; s < Tc; s++) {
        float w = (s <= t) ? __expf(sc[s] - mx) : 0.f;
        sc[s] = w;
        sum += w;
    }
    const float inv = 1.f / sum;

    float4 acc[8] = {};
    #pragma unroll
    for (int s = 0; s < Tc; s++) {
        float w = sc[s];                       // 0 for masked s>t
        #pragma unroll
        for (int j = 0; j < 8; j++) {
            float4 f = vsm[s][j];
            acc[j].x = fmaf(w, f.x, acc[j].x);
            acc[j].y = fmaf(w, f.y, acc[j].y);
            acc[j].z = fmaf(w, f.z, acc[j].z);
            acc[j].w = fmaf(w, f.w, acc[j].w);
        }
    }

    float* outp = att + ((size_t)(b * Tc + t)) * Dc + h * HDc;
    #pragma unroll
    for (int j = 0; j < 8; j++) {
        float4 o = acc[j];
        o.x *= inv; o.y *= inv; o.z *= inv; o.w *= inv;
        *(float4*)(outp + 4 * j) = o;
    }
}

// ------------------------- launcher -----------------------------------------
extern "C" void kernel_launch(void* const* d_in, const int* in_sizes, int n_in,
                              void* d_out, int out_size)
{
    (void)in_sizes; (void)n_in; (void)out_size;
    const int*   idx  = (const int*)  d_in[0];
    const float* tok  = (const float*)d_in[1];
    const float* pos  = (const float*)d_in[2];
    const float* Wq   = (const float*)d_in[3];
    const float* Wk   = (const float*)d_in[4];
    const float* Wv   = (const float*)d_in[5];
    const float* Wo   = (const float*)d_in[6];
    const float* bo   = (const float*)d_in[7];
    const float* ln1g = (const float*)d_in[8];
    const float* ln1b = (const float*)d_in[9];
    const float* W1   = (const float*)d_in[10];
    const float* b1   = (const float*)d_in[11];
    const float* W2   = (const float*)d_in[12];
    const float* b2   = (const float*)d_in[13];
    const float* ln2g = (const float*)d_in[14];
    const float* ln2b = (const float*)d_in[15];
    const float* lnfg = (const float*)d_in[16];
    const float* lnfb = (const float*)d_in[17];
    const float* Wh   = (const float*)d_in[18];
    const float* bh   = (const float*)d_in[19];
    float* out = (float*)d_out;

    float *x, *h, *qkv, *att, *mid, *wqkv;
    cudaGetSymbolAddress((void**)&x,    g_x);
    cudaGetSymbolAddress((void**)&h,    g_h);
    cudaGetSymbolAddress((void**)&qkv,  g_qkv);
    cudaGetSymbolAddress((void**)&att,  g_att);
    cudaGetSymbolAddress((void**)&mid,  g_mid);
    cudaGetSymbolAddress((void**)&wqkv, g_wqkv);

    const int rp_total = Lc * Hc * Dc * HDc;
    repack_kernel<<<(rp_total + 255) / 256, 256>>>(Wq, Wk, Wv, wqkv);
    embed_kernel<<<NTOK, Dc>>>(idx, tok, pos, x);

    const dim3 gQKV (QKVC / 128, NTOK / 128);
    const dim3 gD   (Dc   / 128, NTOK / 128);
    const dim3 gFF  (DFFc / 128, NTOK / 128);
    const dim3 gV   (Vc   / 128, NTOK / 128);
    const int  gLN  = NTOK / 8;

    for (int l = 0; l < Lc; l++) {
        ln_kernel<<<gLN, 256>>>(x, h, ln1g + l * Dc, ln1b + l * Dc);
        gemm_kernel<<<gQKV, 256>>>(h, wqkv + (size_t)l * Dc * QKVC,
                                   nullptr, nullptr, qkv, NTOK, QKVC, Dc, 0);
        attn_kernel<<<Bc * Hc, Tc>>>(qkv, att);
        gemm_kernel<<<gD, 256>>>(att, Wo + (size_t)l * Dc * Dc,
                                 bo + l * Dc, x, x, NTOK, Dc, Dc, 0);
        ln_kernel<<<gLN, 256>>>(x, h, ln2g + l * Dc, ln2b + l * Dc);
        gemm_kernel<<<gFF, 256>>>(h, W1 + (size_t)l * Dc * DFFc,
                                  b1 + l * DFFc, nullptr, mid, NTOK, DFFc, Dc, 1);
        gemm_kernel<<<gD, 256>>>(mid, W2 + (size_t)l * DFFc * Dc,
                                 b2 + l * Dc, x, x, NTOK, Dc, DFFc, 0);
    }

    ln_kernel<<<gLN, 256>>>(x, h, lnfg, lnfb);
    gemm_kernel<<<gV, 256>>>(h, Wh, bh, nullptr, out, NTOK, Vc, Dc, 0);
}

// round 9
// speedup vs baseline: 1.5779x; 1.3256x over previous
#include <cuda_runtime.h>
#include <cuda_bf16.h>
#include <cstdint>

// ---------------------------------------------------------------------------
// BigramTransformer forward — mma.sync (HMMA) bf16-split GEMMs.
// B=2048 T=64 D=128 H=4 HD=32 L=6 V=256 DFF=512
// NOTE: toolchain targets sm_103 (no 'a'), so tcgen05/TMEM are unavailable.
//       mma.sync + ldmatrix are baseline ISA and give tensor-core throughput.
// ---------------------------------------------------------------------------

#define Bc   2048
#define Tc   64
#define Dc   128
#define Hc   4
#define HDc  32
#define Lc   6
#define Vc   256
#define DFFc 512
#define NTOK (Bc * Tc)          /* 131072 */
#define QKVC (3 * Dc)           /* 384    */

// ------------------------- scratch (device globals) ------------------------
__device__ float g_x  [(size_t)NTOK * Dc];
__device__ float g_qkv[(size_t)NTOK * QKVC];
__device__ __nv_bfloat16 g_hh[(size_t)NTOK * Dc],   g_hl[(size_t)NTOK * Dc];
__device__ __nv_bfloat16 g_ah[(size_t)NTOK * Dc],   g_al[(size_t)NTOK * Dc];
__device__ __nv_bfloat16 g_mh[(size_t)NTOK * DFFc], g_ml[(size_t)NTOK * DFFc];
// transposed bf16 weights [N,K] hi/lo
__device__ __nv_bfloat16 g_wqkv_h[Lc * QKVC * Dc],  g_wqkv_l[Lc * QKVC * Dc];
__device__ __nv_bfloat16 g_wo_h  [Lc * Dc * Dc],    g_wo_l  [Lc * Dc * Dc];
__device__ __nv_bfloat16 g_w1_h  [Lc * DFFc * Dc],  g_w1_l  [Lc * DFFc * Dc];
__device__ __nv_bfloat16 g_w2_h  [Lc * Dc * DFFc],  g_w2_l  [Lc * Dc * DFFc];
__device__ __nv_bfloat16 g_whd_h [Vc * Dc],         g_whd_l [Vc * Dc];

// ------------------------- helpers ------------------------------------------
__device__ __forceinline__ uint32_t smem_u32(const void* p) {
    uint32_t a;
    asm("{ .reg .u64 t; cvta.to.shared.u64 t, %1; cvt.u32.u64 %0, t; }"
        : "=r"(a) : "l"(p));
    return a;
}
__device__ __forceinline__ void hilo_store2(float v0, float v1,
                                            __nv_bfloat16* ph, __nv_bfloat16* pl) {
    __nv_bfloat16 h0 = __float2bfloat16(v0), h1 = __float2bfloat16(v1);
    __nv_bfloat162 hh; hh.x = h0; hh.y = h1;
    __nv_bfloat162 ll;
    ll.x = __float2bfloat16(v0 - __bfloat162float(h0));
    ll.y = __float2bfloat16(v1 - __bfloat162float(h1));
    *(__nv_bfloat162*)ph = hh;
    *(__nv_bfloat162*)pl = ll;
}

#define LDMX4(r0, r1, r2, r3, a)                                            \
    asm volatile("ldmatrix.sync.aligned.m8n8.x4.shared.b16 {%0,%1,%2,%3}, [%4];" \
                 : "=r"(r0), "=r"(r1), "=r"(r2), "=r"(r3) : "r"(a))

#define MMA(d, a, b0v, b1v)                                                 \
    asm volatile("mma.sync.aligned.m16n8k16.row.col.f32.bf16.bf16.f32 "     \
                 "{%0,%1,%2,%3}, {%4,%5,%6,%7}, {%8,%9}, {%0,%1,%2,%3};"    \
                 : "+f"((d)[0]), "+f"((d)[1]), "+f"((d)[2]), "+f"((d)[3])   \
                 : "r"((a)[0]), "r"((a)[1]), "r"((a)[2]), "r"((a)[3]),      \
                   "r"(b0v), "r"(b1v))

// ------------------------- weight conversion --------------------------------
// W [K,N] f32 -> out [N,K] bf16 hi/lo.  blockIdx.y = layer slice.
__global__ void convw_kernel(const float* __restrict__ W,
                             __nv_bfloat16* __restrict__ oh,
                             __nv_bfloat16* __restrict__ ol, int K, int N)
{
    const size_t base = (size_t)blockIdx.y * K * N;
    int i = blockIdx.x * 256 + threadIdx.x;
    if (i >= K * N) return;
    int k = i / N, n = i % N;
    float v = W[base + i];
    __nv_bfloat16 h = __float2bfloat16(v);
    oh[base + (size_t)n * K + k] = h;
    ol[base + (size_t)n * K + k] = __float2bfloat16(v - __bfloat162float(h));
}

// Wq/Wk/Wv [L,H,D,HD] -> wqkv_t [L, 384(N), 128(K)] bf16 hi/lo
__global__ void convqkv_kernel(const float* __restrict__ Wq,
                               const float* __restrict__ Wk,
                               const float* __restrict__ Wv,
                               __nv_bfloat16* __restrict__ oh,
                               __nv_bfloat16* __restrict__ ol)
{
    int i = blockIdx.x * 256 + threadIdx.x;
    const int total = Lc * Hc * Dc * HDc;
    if (i >= total) return;
    int e = i % HDc;
    int d = (i / HDc) % Dc;
    int h = (i / (HDc * Dc)) % Hc;
    int l = i / (HDc * Dc * Hc);
    int src = ((l * Hc + h) * Dc + d) * HDc + e;
    const float vq = Wq[src], vk = Wk[src], vv = Wv[src];
    const int col = h * HDc + e;
    size_t dq = ((size_t)l * QKVC + col) * Dc + d;
    size_t dk = ((size_t)l * QKVC + Dc + col) * Dc + d;
    size_t dv = ((size_t)l * QKVC + 2 * Dc + col) * Dc + d;
    __nv_bfloat16 hq = __float2bfloat16(vq);
    __nv_bfloat16 hk = __float2bfloat16(vk);
    __nv_bfloat16 hv = __float2bfloat16(vv);
    oh[dq] = hq; ol[dq] = __float2bfloat16(vq - __bfloat162float(hq));
    oh[dk] = hk; ol[dk] = __float2bfloat16(vk - __bfloat162float(hk));
    oh[dv] = hv; ol[dv] = __float2bfloat16(vv - __bfloat162float(hv));
}

// ------------------------- embedding ---------------------------------------
__global__ void embed_kernel(const int* __restrict__ idx,
                             const float* __restrict__ tok,
                             const float* __restrict__ pos,
                             float* __restrict__ x)
{
    int n = blockIdx.x;
    int d = threadIdx.x;
    int t = n & (Tc - 1);
    int v = idx[n];
    x[(size_t)n * Dc + d] = tok[v * Dc + d] + pos[t * Dc + d];
}

// ------------------------- layernorm -> bf16 hi/lo (one warp / token) -------
__global__ __launch_bounds__(256) void ln_kernel(const float* __restrict__ in,
                                                 __nv_bfloat16* __restrict__ oh,
                                                 __nv_bfloat16* __restrict__ ol,
                                                 const float* __restrict__ gam,
                                                 const float* __restrict__ bet)
{
    const int warp = threadIdx.x >> 5;
    const int lane = threadIdx.x & 31;
    const size_t n = (size_t)blockIdx.x * 8 + warp;

    float4 v = ((const float4*)(in + n * Dc))[lane];

    float s = v.x + v.y + v.z + v.w;
    #pragma unroll
    for (int o = 16; o > 0; o >>= 1) s += __shfl_xor_sync(0xffffffffu, s, o);
    const float mean = s * (1.0f / Dc);

    float4 c = make_float4(v.x - mean, v.y - mean, v.z - mean, v.w - mean);
    float q = c.x * c.x + c.y * c.y + c.z * c.z + c.w * c.w;
    #pragma unroll
    for (int o = 16; o > 0; o >>= 1) q += __shfl_xor_sync(0xffffffffu, q, o);
    const float r = rsqrtf(q * (1.0f / Dc) + 1e-5f);

    const float4 g = ((const float4*)gam)[lane];
    const float4 b = ((const float4*)bet)[lane];
    float o0 = c.x * r * g.x + b.x;
    float o1 = c.y * r * g.y + b.y;
    float o2 = c.z * r * g.z + b.z;
    float o3 = c.w * r * g.w + b.w;
    hilo_store2(o0, o1, oh + n * Dc + lane * 4,     ol + n * Dc + lane * 4);
    hilo_store2(o2, o3, oh + n * Dc + lane * 4 + 2, ol + n * Dc + lane * 4 + 2);
}

// ------------------------- HMMA GEMM ----------------------------------------
// C[M,N] = act(Ah@Bh^T + Ah@Bl^T + Al@Bh^T + bias) (+res)
// A arrays: [M,K] bf16 row-major; B arrays: [N,K] bf16 row-major.
// M%128==0, N%128==0, K%128==0.  One CTA -> 128x128 output tile.
// smem: 4 tiles of 128 rows x 136 bf16 (272B stride, ldmatrix conflict-free).
#define TROWB 272                 /* padded row stride in bytes  */
#define TILEB (128 * TROWB)       /* 34816 bytes per tile        */
#define HGEMM_SMEM (4 * TILEB)    /* 139264                      */

__global__ __launch_bounds__(256, 1) void hgemm_kernel(
    const __nv_bfloat16* __restrict__ Ah, const __nv_bfloat16* __restrict__ Al,
    const __nv_bfloat16* __restrict__ Bh, const __nv_bfloat16* __restrict__ Bl,
    const float* __restrict__ bias, const float* __restrict__ res,
    float* __restrict__ outf,
    __nv_bfloat16* __restrict__ outh, __nv_bfloat16* __restrict__ outl,
    int M, int N, int K, int relu)
{
    extern __shared__ char smem[];
    const uint32_t sb = smem_u32(smem);

    const int tid = threadIdx.x;
    const int w   = tid >> 5;
    const int l   = tid & 31;
    const int wm  = w & 1;            // 2 m-positions of 64
    const int wn  = w >> 1;           // 4 n-positions of 32
    const int m0  = blockIdx.y * 128;
    const int n0  = blockIdx.x * 128;

    // ldmatrix lane addressing: group g (0..3), idx (0..7)
    const int g    = l >> 3;
    const int idx  = l & 7;
    const int lrow = (g & 1) * 8 + idx;     // row within 16-row tile
    const int g2   = (g >> 1) * 16;         // k-half byte offset

    const uint32_t AHo = sb;
    const uint32_t ALo = sb + TILEB;
    const uint32_t BHo = sb + 2 * TILEB;
    const uint32_t BLo = sb + 3 * TILEB;
    const uint32_t arow = (uint32_t)(wm * 64 + lrow) * TROWB + g2;
    const uint32_t brow = (uint32_t)(wn * 32 + lrow) * TROWB + g2;

    const __nv_bfloat16* gsrc[4] = {
        Ah + (size_t)m0 * K, Al + (size_t)m0 * K,
        Bh + (size_t)n0 * K, Bl + (size_t)n0 * K };

    float acc[4][4][4] = {};

    const int nstep = K >> 7;
    for (int c = 0; c < nstep; c++) {
        if (c) __syncthreads();
        const int ck = c << 7;
        // stage 4 tiles: 128 rows x 128 bf16 each
        #pragma unroll
        for (int t = 0; t < 4; t++) {
            const __nv_bfloat16* src = gsrc[t];
            char* dst = smem + (size_t)t * TILEB;
            #pragma unroll
            for (int i = tid; i < 2048; i += 256) {
                const int r  = i >> 4;
                const int c8 = i & 15;
                const uint4 v = *(const uint4*)(src + (size_t)r * K + ck + c8 * 8);
                *(uint4*)(dst + r * TROWB + c8 * 16) = v;
            }
        }
        __syncthreads();

        #pragma unroll
        for (int ks = 0; ks < 8; ks++) {
            const uint32_t kb = ks * 32;      // k-step byte offset
            uint32_t ah_[4][4], al_[4][4], bh_[2][4], bl_[2][4];
            #pragma unroll
            for (int mt = 0; mt < 4; mt++) {
                const uint32_t ao = arow + mt * (16 * TROWB) + kb;
                LDMX4(ah_[mt][0], ah_[mt][1], ah_[mt][2], ah_[mt][3], AHo + ao);
                LDMX4(al_[mt][0], al_[mt][1], al_[mt][2], al_[mt][3], ALo + ao);
            }
            #pragma unroll
            for (int p = 0; p < 2; p++) {
                const uint32_t bo = brow + p * (16 * TROWB) + kb;
                LDMX4(bh_[p][0], bh_[p][1], bh_[p][2], bh_[p][3], BHo + bo);
                LDMX4(bl_[p][0], bl_[p][1], bl_[p][2], bl_[p][3], BLo + bo);
            }
            #pragma unroll
            for (int mt = 0; mt < 4; mt++) {
                #pragma unroll
                for (int nt = 0; nt < 4; nt++) {
                    const int p = nt >> 1, q = nt & 1;
                    const uint32_t b0h = bh_[p][q], b1h = bh_[p][q + 2];
                    const uint32_t b0l = bl_[p][q], b1l = bl_[p][q + 2];
                    MMA(acc[mt][nt], ah_[mt], b0h, b1h);
                    MMA(acc[mt][nt], ah_[mt], b0l, b1l);
                    MMA(acc[mt][nt], al_[mt], b0h, b1h);
                }
            }
        }
    }

    // epilogue: thread holds C[gr(+8)][gc..gc+1] per 16x8 tile
    const int gr = l >> 2;
    const int gc = (l & 3) * 2;
    #pragma unroll
    for (int mt = 0; mt < 4; mt++) {
        #pragma unroll
        for (int h = 0; h < 2; h++) {
            const size_t row = (size_t)m0 + wm * 64 + mt * 16 + gr + h * 8;
            #pragma unroll
            for (int nt = 0; nt < 4; nt++) {
                const int n = n0 + wn * 32 + nt * 8 + gc;
                float v0 = acc[mt][nt][h * 2];
                float v1 = acc[mt][nt][h * 2 + 1];
                if (bias) {
                    const float2 bb = *(const float2*)(bias + n);
                    v0 += bb.x; v1 += bb.y;
                }
                if (relu) { v0 = fmaxf(v0, 0.f); v1 = fmaxf(v1, 0.f); }
                if (res) {
                    const float2 rr = *(const float2*)(res + row * N + n);
                    v0 += rr.x; v1 += rr.y;
                }
                if (outh) {
                    hilo_store2(v0, v1, outh + row * N + n, outl + row * N + n);
                } else {
                    *(float2*)(outf + row * N + n) = make_float2(v0, v1);
                }
            }
        }
    }
}

// ------------------------- attention: one block per (b,h) -------------------
__global__ __launch_bounds__(Tc) void attn_kernel(const float* __restrict__ qkv,
                                                  __nv_bfloat16* __restrict__ oh,
                                                  __nv_bfloat16* __restrict__ ol)
{
    __shared__ float4 qsm[Tc][HDc / 4];
    __shared__ float4 ksm[Tc][HDc / 4];
    __shared__ float4 vsm[Tc][HDc / 4];

    const int bh  = blockIdx.x;
    const int b   = bh >> 2;
    const int h   = bh & 3;
    const int tid = threadIdx.x;

    const float* row = qkv + ((size_t)(b * Tc + tid)) * QKVC + h * HDc;
    #pragma unroll
    for (int j = 0; j < 8; j++) {
        qsm[tid][j] = *(const float4*)(row + 4 * j);
        ksm[tid][j] = *(const float4*)(row + Dc + 4 * j);
        vsm[tid][j] = *(const float4*)(row + 2 * Dc + 4 * j);
    }
    __syncthreads();

    const int t = tid;
    float q[HDc];
    #pragma unroll
    for (int j = 0; j < 8; j++) {
        float4 f = qsm[t][j];
        q[4 * j] = f.x; q[4 * j + 1] = f.y; q[4 * j + 2] = f.z; q[4 * j + 3] = f.w;
    }

    const float scale = 0.17677669529663687f;
    float sc[Tc];
    float mx = -1e30f;
    #pragma unroll
    for (int s = 0; s < Tc; s++) {
        float d = 0.f;
        #pragma unroll
        for (int j = 0; j < 8; j++) {
            float4 f = ksm[s][j];
            d = fmaf(q[4 * j],     f.x, d);
            d = fmaf(q[4 * j + 1], f.y, d);
            d = fmaf(q[4 * j + 2], f.z, d);
            d = fmaf(q[4 * j + 3], f.w, d);
        }
        d *= scale;
        sc[s] = d;
        if (s <= t) mx = fmaxf(mx, d);
    }

    float sum = 0.f;
    #pragma unroll
    for (int s = 0; s < Tc; s++) {
        float w = (s <= t) ? __expf(sc[s] - mx) : 0.f;
        sc[s] = w;
        sum += w;
    }
    const float inv = 1.f / sum;

    float4 acc[8] = {};
    #pragma unroll
    for (int s = 0; s < Tc; s++) {
        float w = sc[s];
        #pragma unroll
        for (int j = 0; j < 8; j++) {
            float4 f = vsm[s][j];
            acc[j].x = fmaf(w, f.x, acc[j].x);
            acc[j].y = fmaf(w, f.y, acc[j].y);
            acc[j].z = fmaf(w, f.z, acc[j].z);
            acc[j].w = fmaf(w, f.w, acc[j].w);
        }
    }

    const size_t base = ((size_t)(b * Tc + t)) * Dc + h * HDc;
    #pragma unroll
    for (int j = 0; j < 8; j++) {
        float4 o = acc[j];
        o.x *= inv; o.y *= inv; o.z *= inv; o.w *= inv;
        hilo_store2(o.x, o.y, oh + base + 4 * j,     ol + base + 4 * j);
        hilo_store2(o.z, o.w, oh + base + 4 * j + 2, ol + base + 4 * j + 2);
    }
}

// ------------------------- launcher -----------------------------------------
extern "C" void kernel_launch(void* const* d_in, const int* in_sizes, int n_in,
                              void* d_out, int out_size)
{
    (void)in_sizes; (void)n_in; (void)out_size;
    const int*   idx  = (const int*)  d_in[0];
    const float* tok  = (const float*)d_in[1];
    const float* pos  = (const float*)d_in[2];
    const float* Wq   = (const float*)d_in[3];
    const float* Wk   = (const float*)d_in[4];
    const float* Wv   = (const float*)d_in[5];
    const float* Wo   = (const float*)d_in[6];
    const float* bo   = (const float*)d_in[7];
    const float* ln1g = (const float*)d_in[8];
    const float* ln1b = (const float*)d_in[9];
    const float* W1   = (const float*)d_in[10];
    const float* b1   = (const float*)d_in[11];
    const float* W2   = (const float*)d_in[12];
    const float* b2   = (const float*)d_in[13];
    const float* ln2g = (const float*)d_in[14];
    const float* ln2b = (const float*)d_in[15];
    const float* lnfg = (const float*)d_in[16];
    const float* lnfb = (const float*)d_in[17];
    const float* Wh   = (const float*)d_in[18];
    const float* bhd  = (const float*)d_in[19];
    float* out = (float*)d_out;

    float *x, *qkv;
    __nv_bfloat16 *hh, *hl, *ah, *al, *mh, *ml;
    __nv_bfloat16 *wqh, *wql, *woh, *wol, *w1h, *w1l, *w2h, *w2l, *whh, *whl;
    cudaGetSymbolAddress((void**)&x,   g_x);
    cudaGetSymbolAddress((void**)&qkv, g_qkv);
    cudaGetSymbolAddress((void**)&hh,  g_hh);  cudaGetSymbolAddress((void**)&hl, g_hl);
    cudaGetSymbolAddress((void**)&ah,  g_ah);  cudaGetSymbolAddress((void**)&al, g_al);
    cudaGetSymbolAddress((void**)&mh,  g_mh);  cudaGetSymbolAddress((void**)&ml, g_ml);
    cudaGetSymbolAddress((void**)&wqh, g_wqkv_h); cudaGetSymbolAddress((void**)&wql, g_wqkv_l);
    cudaGetSymbolAddress((void**)&woh, g_wo_h);   cudaGetSymbolAddress((void**)&wol, g_wo_l);
    cudaGetSymbolAddress((void**)&w1h, g_w1_h);   cudaGetSymbolAddress((void**)&w1l, g_w1_l);
    cudaGetSymbolAddress((void**)&w2h, g_w2_h);   cudaGetSymbolAddress((void**)&w2l, g_w2_l);
    cudaGetSymbolAddress((void**)&whh, g_whd_h);  cudaGetSymbolAddress((void**)&whl, g_whd_l);

    cudaFuncSetAttribute(hgemm_kernel,
                         cudaFuncAttributeMaxDynamicSharedMemorySize, HGEMM_SMEM);

    // weight conversion (replayed every call; cheap)
    convqkv_kernel<<<(Lc * Hc * Dc * HDc + 255) / 256, 256>>>(Wq, Wk, Wv, wqh, wql);
    convw_kernel<<<dim3((Dc * Dc + 255) / 256, Lc), 256>>>(Wo, woh, wol, Dc, Dc);
    convw_kernel<<<dim3((Dc * DFFc + 255) / 256, Lc), 256>>>(W1, w1h, w1l, Dc, DFFc);
    convw_kernel<<<dim3((DFFc * Dc + 255) / 256, Lc), 256>>>(W2, w2h, w2l, DFFc, Dc);
    convw_kernel<<<dim3((Dc * Vc + 255) / 256, 1), 256>>>(Wh, whh, whl, Dc, Vc);

    embed_kernel<<<NTOK, Dc>>>(idx, tok, pos, x);

    const int MT = NTOK / 128;
    const dim3 gQKV(QKVC / 128, MT);
    const dim3 gD  (Dc   / 128, MT);
    const dim3 gFF (DFFc / 128, MT);
    const dim3 gV  (Vc   / 128, MT);
    const int  gLN = NTOK / 8;

    for (int l = 0; l < Lc; l++) {
        ln_kernel<<<gLN, 256>>>(x, hh, hl, ln1g + l * Dc, ln1b + l * Dc);
        hgemm_kernel<<<gQKV, 256, HGEMM_SMEM>>>(
            hh, hl, wqh + (size_t)l * QKVC * Dc, wql + (size_t)l * QKVC * Dc,
            nullptr, nullptr, qkv, nullptr, nullptr, NTOK, QKVC, Dc, 0);
        attn_kernel<<<Bc * Hc, Tc>>>(qkv, ah, al);
        hgemm_kernel<<<gD, 256, HGEMM_SMEM>>>(
            ah, al, woh + (size_t)l * Dc * Dc, wol + (size_t)l * Dc * Dc,
            bo + l * Dc, x, x, nullptr, nullptr, NTOK, Dc, Dc, 0);
        ln_kernel<<<gLN, 256>>>(x, hh, hl, ln2g + l * Dc, ln2b + l * Dc);
        hgemm_kernel<<<gFF, 256, HGEMM_SMEM>>>(
            hh, hl, w1h + (size_t)l * DFFc * Dc, w1l + (size_t)l * DFFc * Dc,
            b1 + l * DFFc, nullptr, nullptr, mh, ml, NTOK, DFFc, Dc, 1);
        hgemm_kernel<<<gD, 256, HGEMM_SMEM>>>(
            mh, ml, w2h + (size_t)l * Dc * DFFc, w2l + (size_t)l * Dc * DFFc,
            b2 + l * Dc, x, x, nullptr, nullptr, NTOK, Dc, DFFc, 0);
    }

    ln_kernel<<<gLN, 256>>>(x, hh, hl, lnfg, lnfb);
    hgemm_kernel<<<gV, 256, HGEMM_SMEM>>>(
        hh, hl, whh, whl, bhd, nullptr, out, nullptr, nullptr, NTOK, Vc, Dc, 0);
}